// round 5
// baseline (speedup 1.0000x reference)
#include <cuda_runtime.h>
#include <cuda_bf16.h>
#include <math.h>
#include <stdint.h>

// ===========================================================================
// GraphAttentionInfluence on GB300 (baseline compute_103 target):
//   Layer 1 restructured: logits via folded W~ = W1 @ a; aggregate raw x
//   (384 feats) per head, THEN per-head GEMM z@W1_h (bias+ELU+split fused).
//   GEMMs: mma.sync bf16 HMMA, 3-term hi/lo split, 3-stage cp.async.
// ===========================================================================

#define N_MAX   20480
#define E_MAX   327680
#define ETOT_MAX (N_MAX + E_MAX)

__device__ float g_h2 [(size_t)N_MAX * 256];
__device__ float g_t  [(size_t)N_MAX * 128];
__device__ __nv_bfloat16 g_zh [(size_t)N_MAX * 4 * 384];
__device__ __nv_bfloat16 g_zl [(size_t)N_MAX * 4 * 384];
__device__ __nv_bfloat16 g_h1ph[(size_t)N_MAX * 1024];
__device__ __nv_bfloat16 g_h1pl[(size_t)N_MAX * 1024];
__device__ __nv_bfloat16 g_hh [(size_t)N_MAX * 256];
__device__ __nv_bfloat16 g_hl [(size_t)N_MAX * 256];
__device__ __nv_bfloat16 g_w1h[1024 * 384], g_w1l[1024 * 384];
__device__ __nv_bfloat16 g_w2h[256 * 1024], g_w2l[256 * 1024];
__device__ __nv_bfloat16 g_wph[128 * 256],  g_wpl[128 * 256];
__device__ float g_wt[8 * 384];
__device__ float g_alpha[(size_t)ETOT_MAX * 4];
__device__ float g_ss[N_MAX * 4];
__device__ float g_sd[N_MAX * 4];
__device__ int   g_deg[N_MAX];
__device__ int   g_cnt[N_MAX];
__device__ int   g_rowptr[N_MAX + 1];
__device__ int   g_csrc[ETOT_MAX];

// ---------------------------------------------------------------------------
__device__ __forceinline__ uint32_t smem_u32(const void* p) {
    uint32_t a;
    asm("{ .reg .u64 t; cvta.to.shared.u64 t, %1; cvt.u32.u64 %0, t; }" : "=r"(a) : "l"(p));
    return a;
}
__device__ __forceinline__ void ldsm4(uint32_t& r0, uint32_t& r1, uint32_t& r2, uint32_t& r3,
                                      uint32_t addr) {
    asm volatile("ldmatrix.sync.aligned.m8n8.x4.shared.b16 {%0,%1,%2,%3}, [%4];"
                 : "=r"(r0), "=r"(r1), "=r"(r2), "=r"(r3) : "r"(addr));
}
__device__ __forceinline__ void mma16816(float* d, const uint32_t* a, const uint32_t* b) {
    asm volatile(
        "mma.sync.aligned.m16n8k16.row.col.f32.bf16.bf16.f32 "
        "{%0,%1,%2,%3}, {%4,%5,%6,%7}, {%8,%9}, {%0,%1,%2,%3};"
        : "+f"(d[0]), "+f"(d[1]), "+f"(d[2]), "+f"(d[3])
        : "r"(a[0]), "r"(a[1]), "r"(a[2]), "r"(a[3]), "r"(b[0]), "r"(b[1]));
}
__device__ __forceinline__ void cp16(uint32_t dst, const void* src, int ok) {
    asm volatile("cp.async.cg.shared.global [%0], [%1], 16, %2;"
                 :: "r"(dst), "l"(src), "r"(ok ? 16 : 0));
}
#define CP_COMMIT() asm volatile("cp.async.commit_group;" ::: "memory")
#define CP_WAIT1()  asm volatile("cp.async.wait_group 1;" ::: "memory")
#define CP_WAIT0()  asm volatile("cp.async.wait_group 0;" ::: "memory")

__device__ __forceinline__ void split2(float v, __nv_bfloat16& hi, __nv_bfloat16& lo) {
    hi = __float2bfloat16(v);
    lo = __float2bfloat16(v - __bfloat162float(hi));
}

// ---------------------------------------------------------------------------
// Unified HMMA GEMM. Per z-slice: C = A[M, K] @ B[Nloc, K]^T.
// Block 128x128 output tile, BK=32, 8 warps, 3-stage cp.async.
// act: 0 none, 1 relu, 2 elu. Outputs: optional fp32 Cf and/or bf16 hi/lo.
// ---------------------------------------------------------------------------
__global__ __launch_bounds__(256, 1)
void hmma_gemm_kernel(const __nv_bfloat16* __restrict__ Ahi, const __nv_bfloat16* __restrict__ Alo,
                      int lda, long azstr,
                      const __nv_bfloat16* __restrict__ Bhi, const __nv_bfloat16* __restrict__ Blo,
                      long bzstr,
                      float* __restrict__ Cf,
                      __nv_bfloat16* __restrict__ Ohi, __nv_bfloat16* __restrict__ Olo,
                      int ldc, int czstr,
                      int M, int K, const float* __restrict__ bias, int act) {
    extern __shared__ __align__(128) char smem[];
    constexpr int RS = 80;
    constexpr int HALF = 128 * RS;
    constexpr int STG = 4 * HALF;

    const int tid = threadIdx.x;
    const int wid = tid >> 5, lane = tid & 31;
    const int wm = wid & 3, wn = wid >> 2;
    const int bm = blockIdx.y * 128, bn = blockIdx.x * 128;
    const int grp = lane >> 3, r8 = lane & 7;
    const int z = blockIdx.z;
    uint32_t sb = smem_u32(smem);

    Ahi += (size_t)z * azstr; Alo += (size_t)z * azstr;
    Bhi += (size_t)z * bzstr; Blo += (size_t)z * bzstr;
    const int czoff = z * czstr;

    int c0 = tid, c1 = tid + 256;
    const __nv_bfloat16* bases[4] = {Ahi, Alo, Bhi, Blo};

    auto gload = [&](int slot, int k0) {
        uint32_t stage_off = (uint32_t)slot * STG;
#pragma unroll
        for (int h = 0; h < 4; h++) {
            int stride = (h < 2) ? lda : K;
#pragma unroll
            for (int rep = 0; rep < 2; rep++) {
                int c = rep ? c1 : c0;
                int row = c >> 2, q = c & 3;
                int grow = (h < 2 ? bm : bn) + row;
                int ok = (h < 2) ? (grow < M) : 1;
                const __nv_bfloat16* src = bases[h] + (size_t)grow * stride + k0 + q * 8;
                cp16(sb + stage_off + h * HALF + row * RS + q * 16, src, ok);
            }
        }
    };

    float acc[2][8][4];
#pragma unroll
    for (int i = 0; i < 2; i++)
#pragma unroll
        for (int j = 0; j < 8; j++)
#pragma unroll
            for (int q = 0; q < 4; q++) acc[i][j][q] = 0.f;

    uint32_t a_off[2], b_off[4];
#pragma unroll
    for (int i = 0; i < 2; i++)
        a_off[i] = (uint32_t)((wm * 32 + i * 16 + (grp & 1) * 8 + r8) * RS);
#pragma unroll
    for (int jp = 0; jp < 4; jp++)
        b_off[jp] = (uint32_t)(2 * HALF + (wn * 64 + jp * 16 + (grp >> 1) * 8 + r8) * RS);

    int nk = K >> 5;
    gload(0, 0); CP_COMMIT();
    if (nk > 1) { gload(1, 32); CP_COMMIT(); }

    for (int it = 0; it < nk; it++) {
        if (it + 2 <= nk) CP_WAIT1(); else CP_WAIT0();
        __syncthreads();
        uint32_t sbase = sb + (uint32_t)(it % 3) * STG;

#pragma unroll
        for (int ks = 0; ks < 2; ks++) {
            uint32_t ka = (uint32_t)((ks * 16 + (grp >> 1) * 8) * 2);
            uint32_t kbq = (uint32_t)((ks * 16 + (grp & 1) * 8) * 2);
            uint32_t ahr[2][4], alr[2][4], bhr[4][4], blr[4][4];
#pragma unroll
            for (int i = 0; i < 2; i++) {
                ldsm4(ahr[i][0], ahr[i][1], ahr[i][2], ahr[i][3], sbase + a_off[i] + ka);
                ldsm4(alr[i][0], alr[i][1], alr[i][2], alr[i][3], sbase + HALF + a_off[i] + ka);
            }
#pragma unroll
            for (int jp = 0; jp < 4; jp++) {
                ldsm4(bhr[jp][0], bhr[jp][1], bhr[jp][2], bhr[jp][3], sbase + b_off[jp] + kbq);
                ldsm4(blr[jp][0], blr[jp][1], blr[jp][2], blr[jp][3], sbase + HALF + b_off[jp] + kbq);
            }
#pragma unroll
            for (int i = 0; i < 2; i++)
#pragma unroll
                for (int j = 0; j < 8; j++)
                    mma16816(acc[i][j], ahr[i], &bhr[j >> 1][(j & 1) * 2]);
#pragma unroll
            for (int i = 0; i < 2; i++)
#pragma unroll
                for (int j = 0; j < 8; j++)
                    mma16816(acc[i][j], ahr[i], &blr[j >> 1][(j & 1) * 2]);
#pragma unroll
            for (int i = 0; i < 2; i++)
#pragma unroll
                for (int j = 0; j < 8; j++)
                    mma16816(acc[i][j], alr[i], &bhr[j >> 1][(j & 1) * 2]);
        }
        if (it + 2 < nk) { gload((it + 2) % 3, (it + 2) * 32); CP_COMMIT(); }
    }

#pragma unroll
    for (int i = 0; i < 2; i++) {
        int row0 = bm + wm * 32 + i * 16 + (lane >> 2);
#pragma unroll
        for (int hf = 0; hf < 2; hf++) {
            int row = row0 + hf * 8;
            if (row < M) {
#pragma unroll
                for (int j = 0; j < 8; j++) {
                    int col = bn + wn * 64 + j * 8 + (lane & 3) * 2;
                    float v0 = acc[i][j][hf * 2 + 0];
                    float v1 = acc[i][j][hf * 2 + 1];
                    if (bias) { v0 += bias[czoff + col]; v1 += bias[czoff + col + 1]; }
                    if (act == 1) { v0 = fmaxf(v0, 0.f); v1 = fmaxf(v1, 0.f); }
                    else if (act == 2) {
                        v0 = v0 > 0.f ? v0 : expm1f(v0);
                        v1 = v1 > 0.f ? v1 : expm1f(v1);
                    }
                    size_t idx = (size_t)row * ldc + czoff + col;
                    if (Cf) *reinterpret_cast<float2*>(Cf + idx) = make_float2(v0, v1);
                    if (Ohi) {
                        __nv_bfloat16 h0, l0, h1, l1;
                        split2(v0, h0, l0); split2(v1, h1, l1);
                        *reinterpret_cast<__nv_bfloat162*>(Ohi + idx) = __nv_bfloat162(h0, h1);
                        *reinterpret_cast<__nv_bfloat162*>(Olo + idx) = __nv_bfloat162(l0, l1);
                    }
                }
            }
        }
    }
}

// ---------------------------------------------------------------------------
// operand prep
// ---------------------------------------------------------------------------
__global__ void tsplit_kernel(const float* __restrict__ W, int K, int Nn,
                              __nv_bfloat16* __restrict__ hi, __nv_bfloat16* __restrict__ lo) {
    int i = blockIdx.x * 256 + threadIdx.x;
    if (i < Nn * K) {
        int n = i / K, k = i - n * K;
        __nv_bfloat16 h, l; split2(W[(size_t)k * Nn + n], h, l);
        hi[i] = h; lo[i] = l;
    }
}

// wt[j][k] = sum_c W1[k, head*256+c] * a[head][c];  j<4: a_src heads, j>=4: a_dst
__global__ void wtilde_kernel(const float* __restrict__ W1,
                              const float* __restrict__ a_src, const float* __restrict__ a_dst,
                              float* __restrict__ wt) {
    int j = blockIdx.x;           // 0..7
    int k = threadIdx.x;          // 0..383
    int head = j & 3;
    const float* a = (j < 4 ? a_src : a_dst) + head * 256;
    const float* wr = W1 + (size_t)k * 1024 + head * 256;
    float s = 0.f;
#pragma unroll 8
    for (int c = 0; c < 256; c++) s = fmaf(wr[c], a[c], s);
    wt[j * 384 + k] = s;
}

// s[n, j] = <x[n,:], wt[j,:]>  -> ss (j<4), sd (j>=4)
__global__ void sgem_kernel(const float* __restrict__ x, const float* __restrict__ wt,
                            float* __restrict__ ss, float* __restrict__ sd) {
    int n = blockIdx.x;
    int j = threadIdx.x >> 5, lane = threadIdx.x & 31;
    const float* xr = x + (size_t)n * 384;
    const float* wr = wt + j * 384;
    float s = 0.f;
#pragma unroll
    for (int i = 0; i < 3; i++) {
        int k = lane * 4 + i * 128;
        float4 xv = *reinterpret_cast<const float4*>(xr + k);
        float4 wv = *reinterpret_cast<const float4*>(wr + k);
        s += xv.x * wv.x + xv.y * wv.y + xv.z * wv.z + xv.w * wv.w;
    }
#pragma unroll
    for (int o = 16; o; o >>= 1) s += __shfl_down_sync(0xFFFFFFFFu, s, o);
    if (lane == 0) {
        if (j < 4) ss[n * 4 + j] = s;
        else       sd[n * 4 + (j - 4)] = s;
    }
}

// ---------------------------------------------------------------------------
// CSR build
// ---------------------------------------------------------------------------
__global__ void zero2_kernel(int* a, int* b, int n) {
    int i = blockIdx.x * 256 + threadIdx.x;
    if (i < n) { a[i] = 0; b[i] = 0; }
}
__global__ void hist_kernel(const int* __restrict__ dst, int E, int N, int* __restrict__ deg) {
    int e = blockIdx.x * 256 + threadIdx.x;
    if (e < E + N) atomicAdd(&deg[(e < E) ? dst[e] : (e - E)], 1);
}
__global__ void scan_kernel(const int* __restrict__ deg, int* __restrict__ rowptr, int N, int Etot) {
    __shared__ int part[1024];
    int tid = threadIdx.x;
    int chunk = (N + 1023) >> 10;
    int lo = tid * chunk, hi = min(lo + chunk, N);
    int s = 0;
    for (int i = lo; i < hi; i++) s += deg[i];
    part[tid] = s; __syncthreads();
    for (int off = 1; off < 1024; off <<= 1) {
        int v = (tid >= off) ? part[tid - off] : 0;
        __syncthreads(); part[tid] += v; __syncthreads();
    }
    int run = tid ? part[tid - 1] : 0;
    for (int i = lo; i < hi; i++) { rowptr[i] = run; run += deg[i]; }
    if (tid == 0) rowptr[N] = Etot;
}
__global__ void scatter_kernel(const int* __restrict__ src, const int* __restrict__ dst,
                               int E, int N, const int* __restrict__ rowptr,
                               int* __restrict__ cnt, int* __restrict__ csrc) {
    int e = blockIdx.x * 256 + threadIdx.x;
    if (e < E + N) {
        int d, s;
        if (e < E) { d = dst[e]; s = src[e]; } else { d = e - E; s = e - E; }
        csrc[rowptr[d] + atomicAdd(&cnt[d], 1)] = s;
    }
}

// ---------------------------------------------------------------------------
__device__ __forceinline__ unsigned fenc(float f) {
    unsigned u = __float_as_uint(f);
    return (u >> 31) ? ~u : (u | 0x80000000u);
}
__device__ __forceinline__ float fdec(unsigned u) {
    return (u >> 31) ? __uint_as_float(u & 0x7FFFFFFFu) : __uint_as_float(~u);
}

// ---------------------------------------------------------------------------
// Layer-1 attention: softmax over 4 heads + aggregate raw x (384 feats).
// z[n, h, :] = (sum_j alpha_jh * x_srcj) -> bf16 hi/lo.  blockDim = 96.
// ---------------------------------------------------------------------------
__global__ void attn1_kernel(const float* __restrict__ x,
                             const float* __restrict__ s_src, const float* __restrict__ s_dst,
                             const int* __restrict__ rowptr, const int* __restrict__ csrc,
                             float* __restrict__ alpha,
                             __nv_bfloat16* __restrict__ zh, __nv_bfloat16* __restrict__ zl) {
    int n = blockIdx.x, tid = threadIdx.x;
    int base = rowptr[n];
    int deg = rowptr[n + 1] - base;

    __shared__ unsigned smax[4];
    __shared__ float ssum[4], sinv[4];
    if (tid < 4) { smax[tid] = 0u; ssum[tid] = 0.f; }
    __syncthreads();

    float sdn[4];
#pragma unroll
    for (int h = 0; h < 4; h++) sdn[h] = s_dst[n * 4 + h];

    int tot = deg * 4;
    for (int idx = tid; idx < tot; idx += 96) {
        int j = idx >> 2, h = idx & 3;
        int s = csrc[base + j];
        float v = s_src[s * 4 + h] + sdn[h];
        v = v > 0.f ? v : 0.2f * v;
        alpha[(size_t)(base + j) * 4 + h] = v;
        atomicMax(&smax[h], fenc(v));
    }
    __syncthreads();
    float m[4];
#pragma unroll
    for (int h = 0; h < 4; h++) m[h] = fdec(smax[h]);
    for (int idx = tid; idx < tot; idx += 96) {
        int j = idx >> 2, h = idx & 3;
        size_t p = (size_t)(base + j) * 4 + h;
        float ex = __expf(alpha[p] - m[h]);
        alpha[p] = ex;
        atomicAdd(&ssum[h], ex);
    }
    __syncthreads();
    if (tid < 4) sinv[tid] = 1.f / (ssum[tid] + 1e-16f);
    __syncthreads();

    float4 acc[4];
#pragma unroll
    for (int h = 0; h < 4; h++) acc[h] = make_float4(0.f, 0.f, 0.f, 0.f);

    for (int j = 0; j < deg; j++) {
        int s = csrc[base + j];
        float4 av = *reinterpret_cast<const float4*>(&alpha[(size_t)(base + j) * 4]);
        float4 xv = *reinterpret_cast<const float4*>(x + (size_t)s * 384 + 4 * tid);
        float a[4] = {av.x, av.y, av.z, av.w};
#pragma unroll
        for (int h = 0; h < 4; h++) {
            acc[h].x = fmaf(xv.x, a[h], acc[h].x);
            acc[h].y = fmaf(xv.y, a[h], acc[h].y);
            acc[h].z = fmaf(xv.z, a[h], acc[h].z);
            acc[h].w = fmaf(xv.w, a[h], acc[h].w);
        }
    }

#pragma unroll
    for (int h = 0; h < 4; h++) {
        float inv = sinv[h];
        float4 v = acc[h];
        v.x *= inv; v.y *= inv; v.z *= inv; v.w *= inv;
        size_t off = ((size_t)n * 4 + h) * 384 + 4 * tid;
        __nv_bfloat16 h0, l0, h1, l1, h2, l2, h3, l3;
        split2(v.x, h0, l0); split2(v.y, h1, l1);
        split2(v.z, h2, l2); split2(v.w, h3, l3);
        __nv_bfloat162* ph = reinterpret_cast<__nv_bfloat162*>(zh + off);
        __nv_bfloat162* pl = reinterpret_cast<__nv_bfloat162*>(zl + off);
        ph[0] = __nv_bfloat162(h0, h1); ph[1] = __nv_bfloat162(h2, h3);
        pl[0] = __nv_bfloat162(l0, l1); pl[1] = __nv_bfloat162(l2, l3);
    }
}

// ---------------------------------------------------------------------------
// layer-2 logits + attention (H=1, C=256)
// ---------------------------------------------------------------------------
__global__ void logits2_kernel(const float* __restrict__ hin,
                               const float* __restrict__ a_src, const float* __restrict__ a_dst,
                               float* __restrict__ ss, float* __restrict__ sd) {
    int n = blockIdx.x;
    int lane = threadIdx.x & 31;
    const float* hr = hin + (size_t)n * 256;
    float as_ = 0.f, ad_ = 0.f;
#pragma unroll
    for (int i = 0; i < 2; i++) {
        int c = lane * 4 + i * 128;
        float4 v = *reinterpret_cast<const float4*>(hr + c);
        float4 wa = *reinterpret_cast<const float4*>(a_src + c);
        float4 wd = *reinterpret_cast<const float4*>(a_dst + c);
        as_ += v.x * wa.x + v.y * wa.y + v.z * wa.z + v.w * wa.w;
        ad_ += v.x * wd.x + v.y * wd.y + v.z * wd.z + v.w * wd.w;
    }
#pragma unroll
    for (int o = 16; o; o >>= 1) {
        as_ += __shfl_down_sync(0xFFFFFFFFu, as_, o);
        ad_ += __shfl_down_sync(0xFFFFFFFFu, ad_, o);
    }
    if (lane == 0) { ss[n] = as_; sd[n] = ad_; }
}

__global__ void attn2_kernel(const float* __restrict__ hin,
                             const float* __restrict__ s_src, const float* __restrict__ s_dst,
                             const int* __restrict__ rowptr, const int* __restrict__ csrc,
                             float* __restrict__ alpha, const float* __restrict__ bias,
                             float* __restrict__ out,
                             __nv_bfloat16* __restrict__ outhi, __nv_bfloat16* __restrict__ outlo) {
    int n = blockIdx.x, tid = threadIdx.x;     // blockDim = 64
    int base = rowptr[n];
    int deg = rowptr[n + 1] - base;

    __shared__ unsigned smax0;
    __shared__ float ssum0, sinv0;
    if (tid == 0) { smax0 = 0u; ssum0 = 0.f; }
    __syncthreads();

    float sdn = s_dst[n];
    for (int j = tid; j < deg; j += 64) {
        int s = csrc[base + j];
        float v = s_src[s] + sdn;
        v = v > 0.f ? v : 0.2f * v;
        alpha[base + j] = v;
        atomicMax(&smax0, fenc(v));
    }
    __syncthreads();
    float m = fdec(smax0);
    for (int j = tid; j < deg; j += 64) {
        float ex = __expf(alpha[base + j] - m);
        alpha[base + j] = ex;
        atomicAdd(&ssum0, ex);
    }
    __syncthreads();
    if (tid == 0) sinv0 = 1.f / (ssum0 + 1e-16f);
    __syncthreads();

    float4 acc = make_float4(0.f, 0.f, 0.f, 0.f);
#pragma unroll 4
    for (int j = 0; j < deg; j++) {
        int s = csrc[base + j];
        float a = alpha[base + j];
        float4 hv = *reinterpret_cast<const float4*>(hin + (size_t)s * 256 + 4 * tid);
        acc.x = fmaf(hv.x, a, acc.x);
        acc.y = fmaf(hv.y, a, acc.y);
        acc.z = fmaf(hv.z, a, acc.z);
        acc.w = fmaf(hv.w, a, acc.w);
    }

    float inv = sinv0;
    float4 bv = *reinterpret_cast<const float4*>(bias + 4 * tid);
    float4 v;
    v.x = acc.x * inv + bv.x;
    v.y = acc.y * inv + bv.y;
    v.z = acc.z * inv + bv.z;
    v.w = acc.w * inv + bv.w;
    v.x = v.x > 0.f ? v.x : expm1f(v.x);
    v.y = v.y > 0.f ? v.y : expm1f(v.y);
    v.z = v.z > 0.f ? v.z : expm1f(v.z);
    v.w = v.w > 0.f ? v.w : expm1f(v.w);

    size_t off = (size_t)n * 256 + 4 * tid;
    *reinterpret_cast<float4*>(out + off) = v;
    __nv_bfloat16 h0, l0, h1, l1, h2, l2, h3, l3;
    split2(v.x, h0, l0); split2(v.y, h1, l1);
    split2(v.z, h2, l2); split2(v.w, h3, l3);
    __nv_bfloat162* ph = reinterpret_cast<__nv_bfloat162*>(outhi + off);
    __nv_bfloat162* pl = reinterpret_cast<__nv_bfloat162*>(outlo + off);
    ph[0] = __nv_bfloat162(h0, h1); ph[1] = __nv_bfloat162(h2, h3);
    pl[0] = __nv_bfloat162(l0, l1); pl[1] = __nv_bfloat162(l2, l3);
}

// ---------------------------------------------------------------------------
// mean pool + influence head
// ---------------------------------------------------------------------------
__global__ void zerof_kernel(float* a, int n) {
    int i = blockIdx.x * 256 + threadIdx.x;
    if (i < n) a[i] = 0.f;
}
__global__ void mean_kernel(const float* __restrict__ h, float* __restrict__ gf, int N) {
    int c = threadIdx.x;
    int rows = (N + gridDim.x - 1) / gridDim.x;
    int r0 = blockIdx.x * rows, r1 = min(r0 + rows, N);
    float s = 0.f;
    for (int r = r0; r < r1; r++) s += h[(size_t)r * 256 + c];
    atomicAdd(&gf[c], s / (float)N);
}
__global__ void infl_kernel(const float* __restrict__ t, const float* __restrict__ Wp2,
                            const float* __restrict__ bp2, float* __restrict__ infl, int N) {
    int g = blockIdx.x * blockDim.x + threadIdx.x;
    int n = g >> 5, lane = g & 31;
    if (n >= N) return;
    float4 tv = reinterpret_cast<const float4*>(t + (size_t)n * 128)[lane];
    float4 wv = reinterpret_cast<const float4*>(Wp2)[lane];
    float s = tv.x * wv.x + tv.y * wv.y + tv.z * wv.z + tv.w * wv.w;
#pragma unroll
    for (int o = 16; o; o >>= 1) s += __shfl_down_sync(0xFFFFFFFFu, s, o);
    if (lane == 0) infl[n] = 1.f / (1.f + __expf(-(s + bp2[0])));
}

// ---------------------------------------------------------------------------
extern "C" void kernel_launch(void* const* d_in, const int* in_sizes, int n_in,
                              void* d_out, int out_size) {
    const float* x      = (const float*)d_in[0];
    const int*   ei     = (const int*)d_in[1];
    const float* W1     = (const float*)d_in[2];
    const float* a_src1 = (const float*)d_in[3];
    const float* a_dst1 = (const float*)d_in[4];
    const float* b1     = (const float*)d_in[5];
    const float* W2     = (const float*)d_in[6];
    const float* a_src2 = (const float*)d_in[7];
    const float* a_dst2 = (const float*)d_in[8];
    const float* b2     = (const float*)d_in[9];
    const float* Wp1    = (const float*)d_in[10];
    const float* bp1    = (const float*)d_in[11];
    const float* Wp2    = (const float*)d_in[12];
    const float* bp2    = (const float*)d_in[13];

    int N = in_sizes[0] / 384;
    int E = in_sizes[1] / 2;
    int Etot = E + N;

    float *h2, *t, *alpha, *ss, *sd, *wt;
    __nv_bfloat16 *zh, *zl, *h1ph, *h1pl, *hh, *hl, *w1h, *w1l, *w2h, *w2l, *wph, *wpl;
    int *deg, *cnt, *rowptr, *csrc;
    cudaGetSymbolAddress((void**)&h2, g_h2);
    cudaGetSymbolAddress((void**)&t, g_t);
    cudaGetSymbolAddress((void**)&alpha, g_alpha);
    cudaGetSymbolAddress((void**)&ss, g_ss);
    cudaGetSymbolAddress((void**)&sd, g_sd);
    cudaGetSymbolAddress((void**)&wt, g_wt);
    cudaGetSymbolAddress((void**)&zh, g_zh);
    cudaGetSymbolAddress((void**)&zl, g_zl);
    cudaGetSymbolAddress((void**)&h1ph, g_h1ph);
    cudaGetSymbolAddress((void**)&h1pl, g_h1pl);
    cudaGetSymbolAddress((void**)&hh, g_hh);
    cudaGetSymbolAddress((void**)&hl, g_hl);
    cudaGetSymbolAddress((void**)&w1h, g_w1h);
    cudaGetSymbolAddress((void**)&w1l, g_w1l);
    cudaGetSymbolAddress((void**)&w2h, g_w2h);
    cudaGetSymbolAddress((void**)&w2l, g_w2l);
    cudaGetSymbolAddress((void**)&wph, g_wph);
    cudaGetSymbolAddress((void**)&wpl, g_wpl);
    cudaGetSymbolAddress((void**)&deg, g_deg);
    cudaGetSymbolAddress((void**)&cnt, g_cnt);
    cudaGetSymbolAddress((void**)&rowptr, g_rowptr);
    cudaGetSymbolAddress((void**)&csrc, g_csrc);

    float* out_h  = (float*)d_out;
    float* out_gf = out_h + (size_t)N * 256;
    float* out_in = out_gf + 256;

    cudaFuncSetAttribute(hmma_gemm_kernel, cudaFuncAttributeMaxDynamicSharedMemorySize, 3 * 40960);

    int eb = (Etot + 255) / 256;
    int nb = (N + 255) / 256;
    int mtiles = (N + 127) / 128;

    // CSR build
    zero2_kernel<<<nb, 256>>>(deg, cnt, N);
    hist_kernel<<<eb, 256>>>(ei + E, E, N, deg);
    scan_kernel<<<1, 1024>>>(deg, rowptr, N, Etot);
    scatter_kernel<<<eb, 256>>>(ei, ei + E, E, N, rowptr, cnt, csrc);

    // folded logit weights + per-node logits
    wtilde_kernel<<<8, 384>>>(W1, a_src1, a_dst1, wt);
    sgem_kernel<<<N, 256>>>(x, wt, ss, sd);

    // weight splits
    tsplit_kernel<<<(1024 * 384 + 255) / 256, 256>>>(W1, 384, 1024, w1h, w1l);
    tsplit_kernel<<<(256 * 1024 + 255) / 256, 256>>>(W2, 1024, 256, w2h, w2l);
    tsplit_kernel<<<(128 * 256 + 255) / 256, 256>>>(Wp1, 256, 128, wph, wpl);

    // Layer 1: softmax + aggregate x -> z
    attn1_kernel<<<N, 96>>>(x, ss, sd, rowptr, csrc, alpha, zh, zl);

    // per-head GEMM: h1p[:, h*256:+256] = ELU(z_h @ W1_h + b1_h), fused split
    {
        dim3 g(2, mtiles, 4);
        hmma_gemm_kernel<<<g, 256, 3 * 40960>>>(zh, zl, 1536, 384,
                                                w1h, w1l, (long)256 * 384,
                                                nullptr, h1ph, h1pl, 1024, 256,
                                                N, 384, b1, 2);
    }

    // Layer 2: h2 = h1p @ W2
    {
        dim3 g(2, mtiles, 1);
        hmma_gemm_kernel<<<g, 256, 3 * 40960>>>(h1ph, h1pl, 1024, 0,
                                                w2h, w2l, 0,
                                                h2, nullptr, nullptr, 256, 0,
                                                N, 1024, nullptr, 0);
    }
    logits2_kernel<<<N, 32>>>(h2, a_src2, a_dst2, ss, sd);
    attn2_kernel<<<N, 64>>>(h2, ss, sd, rowptr, csrc, alpha, b2, out_h, hh, hl);

    // pooling
    zerof_kernel<<<1, 256>>>(out_gf, 256);
    mean_kernel<<<128, 256>>>(out_h, out_gf, N);

    // influence MLP: t = relu(h @ Wp1 + bp1)
    {
        dim3 g(1, mtiles, 1);
        hmma_gemm_kernel<<<g, 256, 3 * 40960>>>(hh, hl, 256, 0,
                                                wph, wpl, 0,
                                                t, nullptr, nullptr, 128, 0,
                                                N, 256, bp1, 1);
    }
    infl_kernel<<<(N * 32 + 255) / 256, 256>>>(t, Wp2, bp2, out_in, N);
}